// round 17
// baseline (speedup 1.0000x reference)
#include <cuda_runtime.h>
#include <cuda_bf16.h>
#include <math.h>

#define Bb 64
#define Ss 4096
#define Aa 128
#define FD 512
#define HD 512
#define NCHUNK 32          // s-chunks for context split (4096/128)
#define SCHUNK 128         // s-rows per chunk
#define PBLK 128           // score blocks per batch (4096 rows / 32 rows-per-block)

// ---- scratch (static device globals; no runtime allocation) ----
__device__ float g_proj_hidden[Bb * Aa];                 // 32 KB
__device__ float g_scores[Bb * Ss];                      // exp(score), 1 MB
__device__ float g_psum[Bb * PBLK];                      // per-block sum of exp
__device__ float g_partial[NCHUNK * Bb * FD];            // 4 MB

__device__ __forceinline__ float tanh_approx(float x) {
    float y;
    asm("tanh.approx.f32 %0, %1;" : "=f"(y) : "f"(x));
    return y;
}

// ---------------------------------------------------------------
// K1: proj_hidden[b,a] = sum_h hidden_state[b,h] * W_hidden[a,h]
// ---------------------------------------------------------------
__global__ void k_proj_hidden(const float* __restrict__ hs,
                              const float* __restrict__ W) {
    int warp = (blockIdx.x * blockDim.x + threadIdx.x) >> 5;
    int lane = threadIdx.x & 31;
    if (warp >= Bb * Aa) return;
    int b = warp >> 7;
    int a = warp & (Aa - 1);

    const float4* wrow = (const float4*)(W + (size_t)a * HD);
    const float4* hrow = (const float4*)(hs + (size_t)b * HD);
    float acc = 0.f;
#pragma unroll
    for (int i = 0; i < HD / 128; i++) {
        float4 w4 = wrow[lane + i * 32];
        float4 h4 = hrow[lane + i * 32];
        acc += w4.x * h4.x + w4.y * h4.y + w4.z * h4.z + w4.w * h4.w;
    }
#pragma unroll
    for (int off = 16; off; off >>= 1)
        acc += __shfl_xor_sync(0xFFFFFFFFu, acc, off);
    if (lane == 0) g_proj_hidden[warp] = acc;
}

// ---------------------------------------------------------------
// K2: e[b,s] = exp( sum_a tanh(pi+ph) * w_score ) and a
// deterministic per-block partial sum of e (32 s-rows per block).
// Scores bounded in ~[-9,9] -> exp safe without max subtraction.
// grid: 8192 blocks x 256 (block = 128 consecutive blocks per b)
// ---------------------------------------------------------------
__global__ void k_scores(const float* __restrict__ pi,
                         const float* __restrict__ wscore) {
    int warp = (blockIdx.x * blockDim.x + threadIdx.x) >> 5;
    int lane = threadIdx.x & 31;
    int wid  = threadIdx.x >> 5;           // 0..7
    int srow0 = warp * 4;
    int b  = srow0 >> 12;
    int s0 = srow0 & (Ss - 1);

    const float4* base = (const float4*)pi + ((size_t)b * Ss + s0) * (Aa / 4) + lane;

    // independent prefix: batch all 4 streaming loads (MLP=4)
    float4 p0 = __ldcs(base + 0 * 32);
    float4 p1 = __ldcs(base + 1 * 32);
    float4 p2 = __ldcs(base + 2 * 32);
    float4 p3 = __ldcs(base + 3 * 32);
    float4 ws = ((const float4*)wscore)[lane];

    cudaGridDependencySynchronize();          // wait for k_proj_hidden
    float4 ph = ((const float4*)(g_proj_hidden + b * Aa))[lane];

    float acc[4];
    acc[0] = tanh_approx(p0.x + ph.x) * ws.x + tanh_approx(p0.y + ph.y) * ws.y
           + tanh_approx(p0.z + ph.z) * ws.z + tanh_approx(p0.w + ph.w) * ws.w;
    acc[1] = tanh_approx(p1.x + ph.x) * ws.x + tanh_approx(p1.y + ph.y) * ws.y
           + tanh_approx(p1.z + ph.z) * ws.z + tanh_approx(p1.w + ph.w) * ws.w;
    acc[2] = tanh_approx(p2.x + ph.x) * ws.x + tanh_approx(p2.y + ph.y) * ws.y
           + tanh_approx(p2.z + ph.z) * ws.z + tanh_approx(p2.w + ph.w) * ws.w;
    acc[3] = tanh_approx(p3.x + ph.x) * ws.x + tanh_approx(p3.y + ph.y) * ws.y
           + tanh_approx(p3.z + ph.z) * ws.z + tanh_approx(p3.w + ph.w) * ws.w;

#pragma unroll
    for (int j = 0; j < 4; j++) {
#pragma unroll
        for (int off = 16; off; off >>= 1)
            acc[j] += __shfl_xor_sync(0xFFFFFFFFu, acc[j], off);
    }

    __shared__ float red[8];
    if (lane == 0) {
        float e0 = __expf(acc[0]);
        float e1 = __expf(acc[1]);
        float e2 = __expf(acc[2]);
        float e3 = __expf(acc[3]);
        float* out = g_scores + b * Ss + s0;
        out[0] = e0; out[1] = e1; out[2] = e2; out[3] = e3;
        red[wid] = (e0 + e1) + (e2 + e3);
    }
    __syncthreads();
    if (threadIdx.x == 0) {
        float s = 0.f;
#pragma unroll
        for (int i = 0; i < 8; i++) s += red[i];   // fixed order: deterministic
        g_psum[blockIdx.x] = s;   // blockIdx.x = b * PBLK + local (consecutive)
    }
}

// ---------------------------------------------------------------
// K3: context partials + inline softmax normalization + weights
// output. block = (chunk, b); 128 threads. Each block:
//  1. (PDL prefix) prefetch first 8-row feat batch
//  2. reduce the 128 per-block exp-sums of b (fixed-order tree)
//  3. w = e * inv; write weights[b, s-range] to d_out; keep in smem
//  4. stream SCHUNK s-rows of image_features (MLP=8 batches)
// grid: dim3(NCHUNK, Bb) x 128 = 2048 CTAs
// ---------------------------------------------------------------
__global__ void k_context(const float* __restrict__ feat,
                          float* __restrict__ weights_out) {
    int chunk = blockIdx.x;
    int b     = blockIdx.y;
    int tid   = threadIdx.x;           // owns d = tid*4..tid*4+3
    int s0    = chunk * SCHUNK;

    const float4* f = (const float4*)feat + ((size_t)b * Ss + s0) * (FD / 4) + tid;

    // independent prefix: prefetch first 8-row batch while k_scores runs
    float4 xr0[8];
#pragma unroll
    for (int j = 0; j < 8; j++)
        xr0[j] = __ldcs(f + (size_t)j * (FD / 4));

    cudaGridDependencySynchronize();          // wait for k_scores

    // deterministic reduction of the 128 partial exp-sums for this b
    __shared__ float psh[PBLK];
    psh[tid] = g_psum[b * PBLK + tid];
    __syncthreads();
#pragma unroll
    for (int off = PBLK / 2; off; off >>= 1) {
        if (tid < off) psh[tid] += psh[tid + off];
        __syncthreads();
    }
    float inv = 1.0f / psh[0];

    // weights for this chunk: normalize exp(score), write output, keep in smem
    __shared__ float wsh[SCHUNK];
    float w = g_scores[b * Ss + s0 + tid] * inv;
    wsh[tid] = w;
    weights_out[b * Ss + s0 + tid] = w;
    __syncthreads();

    float4 acc = make_float4(0.f, 0.f, 0.f, 0.f);
#pragma unroll
    for (int j = 0; j < 8; j++) {
        float ww = wsh[j];
        acc.x += ww * xr0[j].x; acc.y += ww * xr0[j].y;
        acc.z += ww * xr0[j].z; acc.w += ww * xr0[j].w;
    }

    for (int s = 8; s < SCHUNK; s += 8) {
        float4 xr[8];
#pragma unroll
        for (int j = 0; j < 8; j++)
            xr[j] = __ldcs(f + (size_t)(s + j) * (FD / 4));
#pragma unroll
        for (int j = 0; j < 8; j++) {
            float ww = wsh[s + j];
            acc.x += ww * xr[j].x; acc.y += ww * xr[j].y;
            acc.z += ww * xr[j].z; acc.w += ww * xr[j].w;
        }
    }
    float4* out = (float4*)(g_partial + ((size_t)chunk * Bb + b) * FD) + tid;
    *out = acc;
}

// ---------------------------------------------------------------
// K4: reduce NCHUNK chunk-partials -> context (deterministic order).
// ---------------------------------------------------------------
__global__ void k_reduce(float* __restrict__ ctx) {
    cudaGridDependencySynchronize();          // wait for k_context
    int i = blockIdx.x * blockDim.x + threadIdx.x;   // [0, Bb*FD)
    float acc = 0.f;
#pragma unroll
    for (int c = 0; c < NCHUNK; c++)
        acc += g_partial[(size_t)c * Bb * FD + i];
    ctx[i] = acc;
}

// ---------------------------------------------------------------
// Non-template PDL launcher (void*-based, no template deduction).
static void launch_pdl(const void* fn, dim3 grid, dim3 block, void** args) {
    cudaLaunchConfig_t cfg = {};
    cfg.gridDim  = grid;
    cfg.blockDim = block;
    cfg.stream   = 0;   // legacy default stream (same as <<<>>>)
    cudaLaunchAttribute attr[1];
    attr[0].id = cudaLaunchAttributeProgrammaticStreamSerialization;
    attr[0].val.programmaticStreamSerializationAllowed = 1;
    cfg.attrs = attr;
    cfg.numAttrs = 1;
    cudaLaunchKernelExC(&cfg, fn, args);
}

extern "C" void kernel_launch(void* const* d_in, const int* in_sizes, int n_in,
                              void* d_out, int out_size) {
    const float* proj_image     = (const float*)d_in[0];  // [B,S,A]
    const float* image_features = (const float*)d_in[1];  // [B,S,FDIM]
    const float* hidden_state   = (const float*)d_in[2];  // [B,HDIM]
    const float* W_hidden       = (const float*)d_in[3];  // [A,HDIM]
    const float* w_score        = (const float*)d_in[4];  // [A]

    float* out     = (float*)d_out;
    float* ctx     = out;              // [B, FDIM]
    float* weights = out + Bb * FD;    // [B, S]

    k_proj_hidden<<<(Bb * Aa * 32) / 256, 256>>>(hidden_state, W_hidden);

    {
        void* args[] = { (void*)&proj_image, (void*)&w_score };
        launch_pdl((const void*)k_scores,
                   dim3((Bb * Ss / 4) * 32 / 256), dim3(256), args);
    }
    {
        void* args[] = { (void*)&image_features, (void*)&weights };
        launch_pdl((const void*)k_context, dim3(NCHUNK, Bb), dim3(128), args);
    }
    {
        void* args[] = { (void*)&ctx };
        launch_pdl((const void*)k_reduce, dim3(Bb), dim3(512), args);
    }
}